// round 2
// baseline (speedup 1.0000x reference)
#include <cuda_runtime.h>
#include <math.h>

#define BATCH 128
#define NSEQ  512
#define SD    256
#define PD    128
#define FDIM  256
#define NIT   30

// ---- scratch (no runtime allocation allowed) ----
__device__ float g_Sp[BATCH * NSEQ * PD];   // 33.5 MB
__device__ float g_Fp[BATCH * NSEQ * PD];   // 33.5 MB
__device__ float g_u[BATCH * NSEQ];
__device__ float g_v[BATCH * NSEQ];

// ============================================================================
// Kernel 1: fused Linear(256->128) + LayerNorm + L2-normalize
// Block: 256 threads = 2 row-groups x 128 cols. 64 rows per block.
// W (256x128 fp32 = 128KB) cached in dynamic smem once per block.
// ============================================================================
__global__ void __launch_bounds__(256) proj_kernel(
    const float* __restrict__ X, const float* __restrict__ W,
    const float* __restrict__ bias, const float* __restrict__ gamma,
    const float* __restrict__ beta, float* __restrict__ out)
{
    extern __shared__ float sm[];
    float* Wsm = sm;                 // SD*PD
    float* xs  = sm + SD * PD;       // 8*SD
    float* red = xs + 8 * SD;        // 16 floats

    const int tid  = threadIdx.x;
    const int p    = tid & 127;      // output column
    const int g    = tid >> 7;       // row group 0/1
    const int warp = tid >> 5;
    const int lane = tid & 31;

    for (int i = tid; i < SD * PD; i += 256) Wsm[i] = W[i];
    const float bp  = bias[p];
    const float gp  = gamma[p];
    const float btp = beta[p];

    const int row0 = blockIdx.x * 64;

    for (int rb = 0; rb < 64; rb += 8) {
        __syncthreads();
        // stage 8 input rows (8 x 256 floats)
        for (int i = tid; i < 8 * SD; i += 256)
            xs[i] = X[(size_t)(row0 + rb + (i >> 8)) * SD + (i & 255)];
        __syncthreads();

        // each thread computes 4 rows x 1 column
        float h[4];
        #pragma unroll
        for (int r = 0; r < 4; r++) h[r] = bp;
        const float* xg = xs + g * 4 * SD;
        #pragma unroll 4
        for (int d = 0; d < SD; d++) {
            const float w = Wsm[d * PD + p];
            h[0] += xg[d]          * w;
            h[1] += xg[SD + d]     * w;
            h[2] += xg[2 * SD + d] * w;
            h[3] += xg[3 * SD + d] * w;
        }

        #pragma unroll
        for (int r = 0; r < 4; r++) {
            // --- LayerNorm over 128 cols (group-wide reduction) ---
            float s1 = h[r], s2 = h[r] * h[r];
            #pragma unroll
            for (int o = 16; o > 0; o >>= 1) {
                s1 += __shfl_xor_sync(0xffffffffu, s1, o);
                s2 += __shfl_xor_sync(0xffffffffu, s2, o);
            }
            __syncthreads();
            if (lane == 0) { red[warp * 2] = s1; red[warp * 2 + 1] = s2; }
            __syncthreads();
            float sum = 0.f, sq = 0.f;
            const int wb = g * 4;
            #pragma unroll
            for (int w2 = 0; w2 < 4; w2++) {
                sum += red[(wb + w2) * 2];
                sq  += red[(wb + w2) * 2 + 1];
            }
            const float mean = sum * (1.f / PD);
            const float var  = sq * (1.f / PD) - mean * mean;
            const float rstd = rsqrtf(var + 1e-5f);
            const float y    = (h[r] - mean) * rstd * gp + btp;

            // --- L2 normalize over 128 cols ---
            float q = y * y;
            #pragma unroll
            for (int o = 16; o > 0; o >>= 1) q += __shfl_xor_sync(0xffffffffu, q, o);
            __syncthreads();
            if (lane == 0) red[warp * 2] = q;
            __syncthreads();
            float nrm = 0.f;
            #pragma unroll
            for (int w2 = 0; w2 < 4; w2++) nrm += red[(wb + w2) * 2];
            nrm = sqrtf(nrm);
            const float inv = 1.f / fmaxf(nrm, 1e-12f);

            const int row = row0 + rb + g * 4 + r;
            out[(size_t)row * PD + p] = y * inv;
        }
    }
}

// ============================================================================
// Kernel 2: K = exp(-clip(1 - Sp·Fp^T, 0, 2)/0.1), written into P region
// Per-batch 512x512 output; 64x64 tile per block, k=128 in 2 chunks of 64.
// ============================================================================
__global__ void __launch_bounds__(256) cosk_kernel(
    const float* __restrict__ Sp, const float* __restrict__ Fp,
    float* __restrict__ Kout)
{
    __shared__ float As[64][65];
    __shared__ float Bs[64][65];

    const int b  = blockIdx.z;
    const int rt = blockIdx.y * 64;
    const int ct = blockIdx.x * 64;
    const float* A  = Sp + ((size_t)b * NSEQ + rt) * PD;
    const float* Bm = Fp + ((size_t)b * NSEQ + ct) * PD;

    const int tid = threadIdx.x;
    const int tx = tid & 15, ty = tid >> 4;
    float acc[4][4] = {};

    for (int kc = 0; kc < PD; kc += 64) {
        for (int i = tid; i < 64 * 64; i += 256) {
            const int r = i >> 6, k = i & 63;
            As[r][k] = A[(size_t)r * PD + kc + k];
            Bs[r][k] = Bm[(size_t)r * PD + kc + k];
        }
        __syncthreads();
        #pragma unroll
        for (int k = 0; k < 64; k++) {
            float a[4], bb[4];
            #pragma unroll
            for (int i = 0; i < 4; i++) a[i] = As[ty * 4 + i][k];
            #pragma unroll
            for (int j = 0; j < 4; j++) bb[j] = Bs[tx * 4 + j][k];
            #pragma unroll
            for (int i = 0; i < 4; i++)
                #pragma unroll
                for (int j = 0; j < 4; j++) acc[i][j] += a[i] * bb[j];
        }
        __syncthreads();
    }

    float* outb = Kout + (size_t)b * NSEQ * NSEQ;
    #pragma unroll
    for (int i = 0; i < 4; i++) {
        const int row = rt + ty * 4 + i;
        #pragma unroll
        for (int j = 0; j < 4; j++) {
            float c = 1.f - acc[i][j];
            c = fminf(fmaxf(c, 0.f), 2.f);
            outb[(size_t)row * NSEQ + ct + tx * 4 + j] = expf(c * -10.0f);
        }
    }
}

// ============================================================================
// Kernel 3: 30 Sinkhorn iterations. One CTA (512 threads) per batch.
// u-step: warp-per-row GEMV; v-step: thread-per-column (naturally coalesced).
// ============================================================================
__global__ void __launch_bounds__(512) sinkhorn_kernel(const float* __restrict__ Kmat)
{
    __shared__ float us[NSEQ], vs[NSEQ];
    const int b = blockIdx.x;
    const float* Kb = Kmat + (size_t)b * NSEQ * NSEQ;
    const int tid = threadIdx.x;
    const int warp = tid >> 5, lane = tid & 31;

    vs[tid] = 1.f;
    __syncthreads();
    const float r = 1.f / NSEQ;

    for (int it = 0; it < NIT; it++) {
        // u = r / (K v + 1e-8)   (u kept UNclipped for the K^T u step, per ref)
        for (int n = warp; n < NSEQ; n += 16) {
            const float* row = Kb + (size_t)n * NSEQ;
            float s = 0.f;
            #pragma unroll
            for (int mb = 0; mb < NSEQ; mb += 128) {
                s += row[mb + lane]       * vs[mb + lane];
                s += row[mb + 32 + lane]  * vs[mb + 32 + lane];
                s += row[mb + 64 + lane]  * vs[mb + 64 + lane];
                s += row[mb + 96 + lane]  * vs[mb + 96 + lane];
            }
            #pragma unroll
            for (int o = 16; o > 0; o >>= 1) s += __shfl_xor_sync(0xffffffffu, s, o);
            if (lane == 0) us[n] = r / (s + 1e-8f);
        }
        __syncthreads();

        // v = c / (K^T u + 1e-8)
        float s = 0.f;
        #pragma unroll 8
        for (int n = 0; n < NSEQ; n++) s += Kb[(size_t)n * NSEQ + tid] * us[n];
        const float vnew = r / (s + 1e-8f);
        __syncthreads();                 // everyone done reading us
        vs[tid] = fminf(fmaxf(vnew, 1e-8f), 1e8f);
        us[tid] = fminf(fmaxf(us[tid], 1e-8f), 1e8f);
        __syncthreads();
    }

    g_u[b * NSEQ + tid] = us[tid];
    g_v[b * NSEQ + tid] = vs[tid];
}

// ============================================================================
// Kernel 4: P = u * K * v, in place on d_out (float4 per thread)
// ============================================================================
__global__ void __launch_bounds__(256) finalize_kernel(
    float* __restrict__ P, const float* __restrict__ u, const float* __restrict__ v)
{
    const size_t idx = (size_t)blockIdx.x * blockDim.x + threadIdx.x;
    const size_t e = idx * 4;
    if (e >= (size_t)BATCH * NSEQ * NSEQ) return;
    const int m = (int)(e & (NSEQ - 1));
    const int n = (int)((e >> 9) & (NSEQ - 1));
    const int b = (int)(e >> 18);
    float4 k = *(float4*)(P + e);
    const float uu = u[b * NSEQ + n];
    const float4 vv = *(const float4*)(v + b * NSEQ + m);
    k.x *= uu * vv.x; k.y *= uu * vv.y; k.z *= uu * vv.z; k.w *= uu * vv.w;
    *(float4*)(P + e) = k;
}

// ============================================================================
// Kernel 5: F_tilde = P @ F  (per batch: 512x512 @ 512x256)
// ============================================================================
__global__ void __launch_bounds__(256) ftilde_kernel(
    const float* __restrict__ P, const float* __restrict__ F, float* __restrict__ out)
{
    __shared__ float Ps[64][33];
    __shared__ float Fs[32][68];

    const int b  = blockIdx.z;
    const int rt = blockIdx.y * 64;   // n
    const int ct = blockIdx.x * 64;   // d
    const float* Pb = P + (size_t)b * NSEQ * NSEQ;
    const float* Fb = F + (size_t)b * NSEQ * FDIM;

    const int tid = threadIdx.x;
    const int tx = tid & 15, ty = tid >> 4;
    float acc[4][4] = {};

    for (int kc = 0; kc < NSEQ; kc += 32) {
        for (int i = tid; i < 64 * 32; i += 256) {
            const int rr = i >> 5, kk = i & 31;
            Ps[rr][kk] = Pb[(size_t)(rt + rr) * NSEQ + kc + kk];
        }
        for (int i = tid; i < 32 * 64; i += 256) {
            const int kk = i >> 6, dd = i & 63;
            Fs[kk][dd] = Fb[(size_t)(kc + kk) * FDIM + ct + dd];
        }
        __syncthreads();
        #pragma unroll
        for (int k = 0; k < 32; k++) {
            float a[4], bb[4];
            #pragma unroll
            for (int i = 0; i < 4; i++) a[i] = Ps[ty * 4 + i][k];
            #pragma unroll
            for (int j = 0; j < 4; j++) bb[j] = Fs[k][tx * 4 + j];
            #pragma unroll
            for (int i = 0; i < 4; i++)
                #pragma unroll
                for (int j = 0; j < 4; j++) acc[i][j] += a[i] * bb[j];
        }
        __syncthreads();
    }

    float* ob = out + (size_t)b * NSEQ * FDIM;
    #pragma unroll
    for (int i = 0; i < 4; i++)
        #pragma unroll
        for (int j = 0; j < 4; j++)
            ob[(size_t)(rt + ty * 4 + i) * FDIM + ct + tx * 4 + j] = acc[i][j];
}

// ============================================================================
extern "C" void kernel_launch(void* const* d_in, const int* in_sizes, int n_in,
                              void* d_out, int out_size)
{
    const float* S      = (const float*)d_in[0];
    const float* F      = (const float*)d_in[1];
    const float* W_s    = (const float*)d_in[2];
    const float* b_s    = (const float*)d_in[3];
    const float* g_s    = (const float*)d_in[4];
    const float* beta_s = (const float*)d_in[5];
    const float* W_f    = (const float*)d_in[6];
    const float* b_f    = (const float*)d_in[7];
    const float* g_f    = (const float*)d_in[8];
    const float* beta_f = (const float*)d_in[9];

    float* outp = (float*)d_out;
    float* Kmat = outp;                               // P region doubles as K scratch
    float* Ft   = outp + (size_t)BATCH * NSEQ * NSEQ; // F_tilde region

    float *Sp, *Fp, *up, *vp;
    cudaGetSymbolAddress((void**)&Sp, g_Sp);
    cudaGetSymbolAddress((void**)&Fp, g_Fp);
    cudaGetSymbolAddress((void**)&up, g_u);
    cudaGetSymbolAddress((void**)&vp, g_v);

    const int smem = (SD * PD + 8 * SD + 16) * (int)sizeof(float); // ~139 KB
    cudaFuncSetAttribute(proj_kernel, cudaFuncAttributeMaxDynamicSharedMemorySize, smem);

    proj_kernel<<<BATCH * NSEQ / 64, 256, smem>>>(S, W_s, b_s, g_s, beta_s, Sp);
    proj_kernel<<<BATCH * NSEQ / 64, 256, smem>>>(F, W_f, b_f, g_f, beta_f, Fp);
    cosk_kernel<<<dim3(8, 8, BATCH), 256>>>(Sp, Fp, Kmat);
    sinkhorn_kernel<<<BATCH, 512>>>(Kmat);
    finalize_kernel<<<(BATCH * NSEQ * NSEQ / 4 + 255) / 256, 256>>>(Kmat, up, vp);
    ftilde_kernel<<<dim3(4, 8, BATCH), 256>>>(Kmat, F, Ft);
}

// round 4
// speedup vs baseline: 2.4276x; 2.4276x over previous
#include <cuda_runtime.h>
#include <math.h>

#define BATCH 128
#define NSEQ  512
#define SD    256
#define PD    128
#define FDIM  256
#define NIT   30

// ---- scratch (no runtime allocation allowed) ----
__device__ float g_Sp[BATCH * NSEQ * PD];   // 33.5 MB
__device__ float g_Fp[BATCH * NSEQ * PD];   // 33.5 MB
__device__ float g_u[BATCH * NSEQ];
__device__ float g_v[BATCH * NSEQ];

// exp(-c/0.1) = 2^(c * -14.4269504089), c in [0,2] -> y in [-28.854, 0]
// degree-8 Taylor of 2^f on [0,1) + exponent bit trick. rel err < 2e-7. No MUFU.
__device__ __forceinline__ float fast_exp_negC(float c) {
    float y  = c * -14.4269504089f;
    float yi = floorf(y);
    float f  = y - yi;
    float p  = 1.3215486790144305e-06f;
    p = p * f + 1.5252733804059837e-05f;
    p = p * f + 1.5403530393381606e-04f;
    p = p * f + 1.3333558146428443e-03f;
    p = p * f + 9.6181291076284770e-03f;
    p = p * f + 5.5504108664821580e-02f;
    p = p * f + 2.4022650695910070e-01f;
    p = p * f + 6.9314718055994530e-01f;
    p = p * f + 1.0f;
    return __int_as_float(((int)yi + 127) << 23) * p;
}

// ============================================================================
// Kernel 1: fused Linear(256->128) + LayerNorm + L2-normalize
// Block 256 threads = (tx 0..15 -> 8 cols) x (ty 0..15 -> 4 rows). Tile 64x128.
// ============================================================================
__global__ void __launch_bounds__(256) proj_kernel(
    const float* __restrict__ X, const float* __restrict__ W,
    const float* __restrict__ bias, const float* __restrict__ gamma,
    const float* __restrict__ beta, float* __restrict__ out)
{
    __shared__ float As[64][33];
    __shared__ float Ws[32][128];
    __shared__ float red[64][34];
    __shared__ float stats[64][2];

    const int tid = threadIdx.x;
    const int tx = tid & 15;
    const int ty = tid >> 4;
    const int row0 = blockIdx.x * 64;
    const int colbase = tx * 8;

    float acc[4][8];
    #pragma unroll
    for (int i = 0; i < 4; i++)
        #pragma unroll
        for (int j = 0; j < 8; j++) acc[i][j] = 0.f;

    for (int kc = 0; kc < SD; kc += 32) {
        #pragma unroll
        for (int p = 0; p < 2; p++) {
            int idx = tid + p * 256;
            int r = idx >> 3, c4 = (idx & 7) * 4;
            float4 v = *(const float4*)&X[(size_t)(row0 + r) * SD + kc + c4];
            As[r][c4] = v.x; As[r][c4 + 1] = v.y; As[r][c4 + 2] = v.z; As[r][c4 + 3] = v.w;
        }
        #pragma unroll
        for (int p = 0; p < 4; p++) {
            int idx = tid + p * 256;
            int k = idx >> 5, c4 = (idx & 31) * 4;
            *(float4*)&Ws[k][c4] = *(const float4*)&W[(size_t)(kc + k) * PD + c4];
        }
        __syncthreads();
        #pragma unroll
        for (int k = 0; k < 32; k++) {
            float a[4];
            #pragma unroll
            for (int i = 0; i < 4; i++) a[i] = As[ty * 4 + i][k];
            float4 b0 = *(float4*)&Ws[k][colbase];
            float4 b1 = *(float4*)&Ws[k][colbase + 4];
            float bb[8] = {b0.x, b0.y, b0.z, b0.w, b1.x, b1.y, b1.z, b1.w};
            #pragma unroll
            for (int i = 0; i < 4; i++)
                #pragma unroll
                for (int j = 0; j < 8; j++) acc[i][j] += a[i] * bb[j];
        }
        __syncthreads();
    }

    float bcol[8], gcol[8], btc[8];
    #pragma unroll
    for (int j = 0; j < 8; j++) {
        bcol[j] = bias[colbase + j];
        gcol[j] = gamma[colbase + j];
        btc[j]  = beta[colbase + j];
    }

    // bias + LN partial sums
    #pragma unroll
    for (int i = 0; i < 4; i++) {
        float s1 = 0.f, s2 = 0.f;
        #pragma unroll
        for (int j = 0; j < 8; j++) {
            float h = acc[i][j] + bcol[j];
            acc[i][j] = h;
            s1 += h; s2 += h * h;
        }
        red[ty * 4 + i][tx * 2] = s1;
        red[ty * 4 + i][tx * 2 + 1] = s2;
    }
    __syncthreads();
    if (tid < 64) {
        float a = 0.f, b2 = 0.f;
        #pragma unroll
        for (int t = 0; t < 16; t++) { a += red[tid][t * 2]; b2 += red[tid][t * 2 + 1]; }
        float mean = a * (1.f / PD);
        float var  = b2 * (1.f / PD) - mean * mean;
        stats[tid][0] = mean;
        stats[tid][1] = rsqrtf(var + 1e-5f);
    }
    __syncthreads();
    #pragma unroll
    for (int i = 0; i < 4; i++) {
        const int row = ty * 4 + i;
        const float mean = stats[row][0], rstd = stats[row][1];
        float q = 0.f;
        #pragma unroll
        for (int j = 0; j < 8; j++) {
            float y = (acc[i][j] - mean) * rstd * gcol[j] + btc[j];
            acc[i][j] = y;
            q += y * y;
        }
        red[row][tx] = q;
    }
    __syncthreads();
    if (tid < 64) {
        float a = 0.f;
        #pragma unroll
        for (int t = 0; t < 16; t++) a += red[tid][t];
        float n = sqrtf(a);
        stats[tid][0] = 1.f / fmaxf(n, 1e-12f);
    }
    __syncthreads();
    #pragma unroll
    for (int i = 0; i < 4; i++) {
        const int row = ty * 4 + i;
        const float inv = stats[row][0];
        float4 o0 = make_float4(acc[i][0] * inv, acc[i][1] * inv, acc[i][2] * inv, acc[i][3] * inv);
        float4 o1 = make_float4(acc[i][4] * inv, acc[i][5] * inv, acc[i][6] * inv, acc[i][7] * inv);
        float* op = out + (size_t)(row0 + row) * PD + colbase;
        *(float4*)op = o0;
        *(float4*)(op + 4) = o1;
    }
}

// ============================================================================
// Kernel 2: K = exp(-clip(1 - Sp·Fp^T,0,2)/0.1). Tile 128x128, microtile 8x8.
// ============================================================================
__global__ void __launch_bounds__(256) cosk_kernel(
    const float* __restrict__ Sp, const float* __restrict__ Fp,
    float* __restrict__ Kout)
{
    __shared__ float As[128][17];   // [row][k]
    __shared__ float Bs[16][132];   // [k][col]  (transposed for conflict-free LDS.128)

    const int b  = blockIdx.z;
    const int rt = blockIdx.y * 128;
    const int ct = blockIdx.x * 128;
    const float* A  = Sp + ((size_t)b * NSEQ + rt) * PD;
    const float* Bm = Fp + ((size_t)b * NSEQ + ct) * PD;

    const int tid = threadIdx.x;
    const int tx = tid & 15, ty = tid >> 4;

    float acc[8][8];
    #pragma unroll
    for (int i = 0; i < 8; i++)
        #pragma unroll
        for (int j = 0; j < 8; j++) acc[i][j] = 0.f;

    for (int kc = 0; kc < PD; kc += 16) {
        #pragma unroll
        for (int p = 0; p < 2; p++) {
            int idx = tid + p * 256;
            int r = idx >> 2, c4 = (idx & 3) * 4;
            float4 v = *(const float4*)&A[(size_t)r * PD + kc + c4];
            As[r][c4] = v.x; As[r][c4 + 1] = v.y; As[r][c4 + 2] = v.z; As[r][c4 + 3] = v.w;
        }
        #pragma unroll
        for (int p = 0; p < 2; p++) {
            int idx = tid + p * 256;
            int m = idx >> 2, c4 = (idx & 3) * 4;
            float4 v = *(const float4*)&Bm[(size_t)m * PD + kc + c4];
            Bs[c4][m] = v.x; Bs[c4 + 1][m] = v.y; Bs[c4 + 2][m] = v.z; Bs[c4 + 3][m] = v.w;
        }
        __syncthreads();
        #pragma unroll
        for (int k = 0; k < 16; k++) {
            float a[8];
            #pragma unroll
            for (int i = 0; i < 8; i++) a[i] = As[ty * 8 + i][k];
            float4 b0 = *(float4*)&Bs[k][tx * 8];
            float4 b1 = *(float4*)&Bs[k][tx * 8 + 4];
            float bb[8] = {b0.x, b0.y, b0.z, b0.w, b1.x, b1.y, b1.z, b1.w};
            #pragma unroll
            for (int i = 0; i < 8; i++)
                #pragma unroll
                for (int j = 0; j < 8; j++) acc[i][j] += a[i] * bb[j];
        }
        __syncthreads();
    }

    float* outb = Kout + (size_t)b * NSEQ * NSEQ;
    #pragma unroll
    for (int i = 0; i < 8; i++) {
        const int row = rt + ty * 8 + i;
        float o[8];
        #pragma unroll
        for (int j = 0; j < 8; j++) {
            float c = 1.f - acc[i][j];
            c = fminf(fmaxf(c, 0.f), 2.f);
            o[j] = fast_exp_negC(c);
        }
        float* op = outb + (size_t)row * NSEQ + ct + tx * 8;
        *(float4*)op       = make_float4(o[0], o[1], o[2], o[3]);
        *(float4*)(op + 4) = make_float4(o[4], o[5], o[6], o[7]);
    }
}

// ============================================================================
// Kernel 3: 30 Sinkhorn iterations, ONE pass over K per iteration.
// 1024 threads per CTA, 1 CTA per batch. Each warp owns 16 rows; while
// computing u[n] it accumulates u[n]*K[n,:] into register partials of K^T u.
// v kept in registers (16 cols per lane), cross-warp reduce via smem.
// ============================================================================
__global__ void __launch_bounds__(1024) sinkhorn_kernel(
    const float* __restrict__ K, float* __restrict__ gu, float* __restrict__ gv)
{
    extern __shared__ float sm[];
    float* vs   = sm;            // 512
    float* us   = sm + 512;      // 512
    float* part = sm + 1024;     // 32*512

    const int b = blockIdx.x;
    const float* Kb = K + (size_t)b * NSEQ * NSEQ;
    const int tid = threadIdx.x;
    const int w = tid >> 5, lane = tid & 31;
    const float rc = 1.0f / NSEQ;

    float vreg[16];
    #pragma unroll
    for (int j = 0; j < 16; j++) vreg[j] = 1.0f;

    for (int it = 0; it < NIT; it++) {
        float kt[16];
        #pragma unroll
        for (int j = 0; j < 16; j++) kt[j] = 0.f;

        #pragma unroll 2
        for (int rr = 0; rr < 16; rr++) {
            const int row = w * 16 + rr;
            const float4* rp = (const float4*)(Kb + (size_t)row * NSEQ);
            float4 x0 = rp[lane];
            float4 x1 = rp[32 + lane];
            float4 x2 = rp[64 + lane];
            float4 x3 = rp[96 + lane];
            float s = x0.x * vreg[0]  + x0.y * vreg[1]  + x0.z * vreg[2]  + x0.w * vreg[3]
                    + x1.x * vreg[4]  + x1.y * vreg[5]  + x1.z * vreg[6]  + x1.w * vreg[7]
                    + x2.x * vreg[8]  + x2.y * vreg[9]  + x2.z * vreg[10] + x2.w * vreg[11]
                    + x3.x * vreg[12] + x3.y * vreg[13] + x3.z * vreg[14] + x3.w * vreg[15];
            #pragma unroll
            for (int o = 16; o > 0; o >>= 1) s += __shfl_xor_sync(0xffffffffu, s, o);
            const float un = rc / (s + 1e-8f);          // unclipped for K^T u (matches ref order)
            kt[0]  += un * x0.x; kt[1]  += un * x0.y; kt[2]  += un * x0.z; kt[3]  += un * x0.w;
            kt[4]  += un * x1.x; kt[5]  += un * x1.y; kt[6]  += un * x1.z; kt[7]  += un * x1.w;
            kt[8]  += un * x2.x; kt[9]  += un * x2.y; kt[10] += un * x2.z; kt[11] += un * x2.w;
            kt[12] += un * x3.x; kt[13] += un * x3.y; kt[14] += un * x3.z; kt[15] += un * x3.w;
            if (lane == 0) us[row] = fminf(fmaxf(un, 1e-8f), 1e8f);
        }
        float4* pw = (float4*)(part + w * NSEQ);
        pw[lane]      = make_float4(kt[0],  kt[1],  kt[2],  kt[3]);
        pw[32 + lane] = make_float4(kt[4],  kt[5],  kt[6],  kt[7]);
        pw[64 + lane] = make_float4(kt[8],  kt[9],  kt[10], kt[11]);
        pw[96 + lane] = make_float4(kt[12], kt[13], kt[14], kt[15]);
        __syncthreads();
        if (tid < NSEQ) {
            float a = 0.f;
            #pragma unroll 8
            for (int w2 = 0; w2 < 32; w2++) a += part[w2 * NSEQ + tid];
            const float vn = rc / (a + 1e-8f);
            vs[tid] = fminf(fmaxf(vn, 1e-8f), 1e8f);
        }
        __syncthreads();
        const float4* vv = (const float4*)vs;
        float4 v0 = vv[lane], v1 = vv[32 + lane], v2 = vv[64 + lane], v3 = vv[96 + lane];
        vreg[0]  = v0.x; vreg[1]  = v0.y; vreg[2]  = v0.z; vreg[3]  = v0.w;
        vreg[4]  = v1.x; vreg[5]  = v1.y; vreg[6]  = v1.z; vreg[7]  = v1.w;
        vreg[8]  = v2.x; vreg[9]  = v2.y; vreg[10] = v2.z; vreg[11] = v2.w;
        vreg[12] = v3.x; vreg[13] = v3.y; vreg[14] = v3.z; vreg[15] = v3.w;
    }
    if (tid < NSEQ) {
        gu[b * NSEQ + tid] = us[tid];
        gv[b * NSEQ + tid] = vs[tid];
    }
}

// ============================================================================
// Kernel 4: fused finalize + GEMM.
// P = u*K*v written in place over K (this block exclusively owns its rows),
// F_tilde = P @ F. Tile 64(n) x 256(d), microtile 8x8, k-chunk 32.
// ============================================================================
__global__ void __launch_bounds__(256) ftilde_kernel(
    float* __restrict__ P, const float* __restrict__ F,
    const float* __restrict__ u, const float* __restrict__ v,
    float* __restrict__ out)
{
    __shared__ float Ps[64][33];    // [row][k]
    __shared__ float Fs[32][260];   // [k][d]

    const int b  = blockIdx.y;
    const int rt = blockIdx.x * 64;
    float* Pb = P + ((size_t)b * NSEQ + rt) * NSEQ;
    const float* Fb = F + (size_t)b * NSEQ * FDIM;
    const float* ub = u + b * NSEQ;
    const float* vb = v + b * NSEQ;

    const int tid = threadIdx.x;
    const int tx = tid & 31, ty = tid >> 5;

    float acc[8][8];
    #pragma unroll
    for (int i = 0; i < 8; i++)
        #pragma unroll
        for (int j = 0; j < 8; j++) acc[i][j] = 0.f;

    for (int kc = 0; kc < NSEQ; kc += 32) {
        // load K chunk, scale to P, write back, stash in smem
        #pragma unroll
        for (int p = 0; p < 2; p++) {
            int idx = tid + p * 256;
            int r = idx >> 3, c4 = (idx & 7) * 4;
            float* kp = Pb + (size_t)r * NSEQ + kc + c4;
            float4 kv = *(float4*)kp;
            const float uu = __ldg(&ub[rt + r]);
            const float4 vvv = *(const float4*)&vb[kc + c4];
            kv.x *= uu * vvv.x; kv.y *= uu * vvv.y; kv.z *= uu * vvv.z; kv.w *= uu * vvv.w;
            *(float4*)kp = kv;
            Ps[r][c4] = kv.x; Ps[r][c4 + 1] = kv.y; Ps[r][c4 + 2] = kv.z; Ps[r][c4 + 3] = kv.w;
        }
        // load F chunk [32k x 256d]
        #pragma unroll
        for (int p = 0; p < 8; p++) {
            int idx = tid + p * 256;
            int k = idx >> 6, d4 = (idx & 63) * 4;
            *(float4*)&Fs[k][d4] = *(const float4*)&Fb[(size_t)(kc + k) * FDIM + d4];
        }
        __syncthreads();
        #pragma unroll
        for (int k = 0; k < 32; k++) {
            float a[8];
            #pragma unroll
            for (int i = 0; i < 8; i++) a[i] = Ps[ty * 8 + i][k];
            float4 b0 = *(float4*)&Fs[k][tx * 8];
            float4 b1 = *(float4*)&Fs[k][tx * 8 + 4];
            float bb[8] = {b0.x, b0.y, b0.z, b0.w, b1.x, b1.y, b1.z, b1.w};
            #pragma unroll
            for (int i = 0; i < 8; i++)
                #pragma unroll
                for (int j = 0; j < 8; j++) acc[i][j] += a[i] * bb[j];
        }
        __syncthreads();
    }

    float* ob = out + ((size_t)b * NSEQ + rt) * FDIM;
    #pragma unroll
    for (int i = 0; i < 8; i++) {
        float* op = ob + (size_t)(ty * 8 + i) * FDIM + tx * 8;
        *(float4*)op       = make_float4(acc[i][0], acc[i][1], acc[i][2], acc[i][3]);
        *(float4*)(op + 4) = make_float4(acc[i][4], acc[i][5], acc[i][6], acc[i][7]);
    }
}

// ============================================================================
extern "C" void kernel_launch(void* const* d_in, const int* in_sizes, int n_in,
                              void* d_out, int out_size)
{
    const float* S      = (const float*)d_in[0];
    const float* F      = (const float*)d_in[1];
    const float* W_s    = (const float*)d_in[2];
    const float* b_s    = (const float*)d_in[3];
    const float* g_s    = (const float*)d_in[4];
    const float* beta_s = (const float*)d_in[5];
    const float* W_f    = (const float*)d_in[6];
    const float* b_f    = (const float*)d_in[7];
    const float* g_f    = (const float*)d_in[8];
    const float* beta_f = (const float*)d_in[9];

    float* outp = (float*)d_out;
    float* Kmat = outp;                               // P region doubles as K scratch
    float* Ft   = outp + (size_t)BATCH * NSEQ * NSEQ; // F_tilde region

    float *Sp, *Fp, *up, *vp;
    cudaGetSymbolAddress((void**)&Sp, g_Sp);
    cudaGetSymbolAddress((void**)&Fp, g_Fp);
    cudaGetSymbolAddress((void**)&up, g_u);
    cudaGetSymbolAddress((void**)&vp, g_v);

    const int smem_sink = (1024 + 32 * NSEQ) * (int)sizeof(float); // 68 KB
    cudaFuncSetAttribute(sinkhorn_kernel, cudaFuncAttributeMaxDynamicSharedMemorySize, smem_sink);

    proj_kernel<<<BATCH * NSEQ / 64, 256>>>(S, W_s, b_s, g_s, beta_s, Sp);
    proj_kernel<<<BATCH * NSEQ / 64, 256>>>(F, W_f, b_f, g_f, beta_f, Fp);
    cosk_kernel<<<dim3(4, 4, BATCH), 256>>>(Sp, Fp, Kmat);
    sinkhorn_kernel<<<BATCH, 1024, smem_sink>>>(Kmat, up, vp);
    ftilde_kernel<<<dim3(NSEQ / 64, BATCH), 256>>>(Kmat, F, up, vp, Ft);
}